// round 4
// baseline (speedup 1.0000x reference)
#include <cuda_runtime.h>
#include <cuda_bf16.h>

// YOLO layer: x [B=16, C=255, 64, 64] fp32, anchors [3,2] fp32.
// pred = x.reshape(B, 3, 85, 64, 64).transpose(0,1,3,4,2)
// Outputs concatenated in d_out (float32):
//   boxes [B,3,64,64,4]  : 786,432  elems at offset 0
//   conf  [B,3,64,64]    : 196,608  elems at offset 786,432
//   cls   [B,3,64,64,80] : 15,728,640 elems at offset 983,040
//
// box0 = (sigmoid(ch0) + i) / 64      (i = row index, axis 2)
// box1 = (sigmoid(ch1) + j) / 64      (j = col index, axis 3)
// box2 = exp(ch2) * anchors[a][0]     (anchor_w*g0 / g0 cancels)
// box3 = exp(ch3) * anchors[a][1]
// conf = sigmoid(ch4); cls = sigmoid(ch5..84)
//
// Strategy: HBM-bound transpose. Per block: one (b,a), TP=64 positions,
// all 85 channels staged through smem. Coalesced float4 loads along the
// spatial dim; coalesced contiguous stores in the output layout.

#define NT 256
#define TP 64

__device__ __forceinline__ float sigf(float v) {
    return 1.0f / (1.0f + __expf(-v));
}

__global__ __launch_bounds__(NT) void yolo_kernel(
    const float* __restrict__ x,
    const float* __restrict__ anchors,
    float* __restrict__ out)
{
    constexpr int A  = 3;
    constexpr int NC = 80;
    constexpr int CH = 85;          // NC + 5
    constexpr int G  = 64;
    constexpr int P  = G * G;       // 4096 positions per (b,a)
    constexpr int Btot = 16;
    constexpr int BOX_OFF  = 0;
    constexpr int CONF_OFF = Btot * A * P * 4;        // 786432
    constexpr int CLS_OFF  = CONF_OFF + Btot * A * P; // 983040

    __shared__ float tile[CH][TP + 1];   // pitch 65 -> bank = (c + p) % 32

    constexpr int TILES_PER_BA = P / TP; // 64
    const int blk = blockIdx.x;
    const int ba  = blk / TILES_PER_BA;
    const int p0  = (blk - ba * TILES_PER_BA) * TP;
    const int a   = ba % A;
    const int t   = threadIdx.x;

    // ---- Load: 85 channels x 64 positions, float4-coalesced along spatial ----
    const float* xin = x + (size_t)ba * CH * P + p0;
    for (int idx = t; idx < CH * (TP / 4); idx += NT) {
        const int c = idx / (TP / 4);
        const int q = idx - c * (TP / 4);
        float4 v = reinterpret_cast<const float4*>(xin + c * P)[q];
        tile[c][q * 4 + 0] = v.x;
        tile[c][q * 4 + 1] = v.y;
        tile[c][q * 4 + 2] = v.z;
        tile[c][q * 4 + 3] = v.w;
    }
    __syncthreads();

    const float aw = __ldg(anchors + a * 2 + 0);
    const float ah = __ldg(anchors + a * 2 + 1);

    // ---- cls: 64 positions x 80 classes, contiguous coalesced stores ----
    float* ocls = out + CLS_OFF + (ba * P + p0) * NC;
    #pragma unroll 4
    for (int idx = t; idx < TP * NC; idx += NT) {
        const int p = idx / NC;
        const int c = idx - p * NC;
        ocls[idx] = sigf(tile[5 + c][p]);
    }

    // ---- conf: 64 contiguous floats ----
    if (t < TP) {
        out[CONF_OFF + ba * P + p0 + t] = sigf(tile[4][t]);
    }

    // ---- boxes: 64 positions x 4, contiguous 256 floats ----
    {
        const int p  = t >> 2;
        const int k  = t & 3;
        const int pg = p0 + p;
        float v;
        if (k == 0)      v = (sigf(tile[0][p]) + (float)(pg >> 6)) * (1.0f / 64.0f);
        else if (k == 1) v = (sigf(tile[1][p]) + (float)(pg & 63)) * (1.0f / 64.0f);
        else if (k == 2) v = __expf(tile[2][p]) * aw;
        else             v = __expf(tile[3][p]) * ah;
        out[BOX_OFF + (ba * P + pg) * 4 + k] = v;
    }
}

extern "C" void kernel_launch(void* const* d_in, const int* in_sizes, int n_in,
                              void* d_out, int out_size) {
    const float* x       = (const float*)d_in[0];
    const float* anchors = (const float*)d_in[1];
    float*       out     = (float*)d_out;
    // 16 batches * 3 anchors * (4096/64) tiles = 3072 blocks
    yolo_kernel<<<3072, NT>>>(x, anchors, out);
}

// round 7
// speedup vs baseline: 1.4028x; 1.4028x over previous
#include <cuda_runtime.h>
#include <cuda_bf16.h>

// YOLO layer: x [B=16, C=255, 64, 64] fp32, anchors [3,2] fp32.
// pred = x.reshape(B, 3, 85, 64, 64).transpose(0,1,3,4,2)
// Outputs concatenated in d_out (float32):
//   boxes [B,3,64,64,4]  : 786,432    elems at offset 0
//   conf  [B,3,64,64]    : 196,608    elems at offset 786,432
//   cls   [B,3,64,64,80] : 15,728,640 elems at offset 983,040
//
// box0 = (sigmoid(ch0) + i) / 64   (i = p>>6)
// box1 = (sigmoid(ch1) + j) / 64   (j = p&63)
// box2 = exp(ch2) * anchors[a][0]  (anchor_w*g0/g0 cancels)
// box3 = exp(ch3) * anchors[a][1]
// conf = sigmoid(ch4); cls = sigmoid(ch5..84)
//
// R5: identical to R4 (R4 bench died with "system not yet initialized" —
// harness-side GPU init failure in the container, before kernel code ran;
// infra flake, not a kernel fault). Re-benching the instruction-diet
// rewrite: all-float4 gmem traffic (LDG.128/STS.128/STG.128),
// division-free indexing, fully unrolled inner loops. Smem pitch 68
// floats (17 float4) keeps float4 alignment; bank stride 4 -> at most
// 2-way LDS conflicts on the transpose reads.

#define NT 256
#define TP 64
#define PITCH 68            // floats per smem channel row (16 f4 data + 1 f4 pad)
#define PITCH4 17           // float4s per row

__device__ __forceinline__ float sigf(float v) {
    return __fdividef(1.0f, 1.0f + __expf(-v));   // FMUL + MUFU.EX2 + FADD + MUFU.RCP
}

__global__ __launch_bounds__(NT) void yolo_kernel(
    const float* __restrict__ x,
    const float* __restrict__ anchors,
    float* __restrict__ out)
{
    constexpr int A    = 3;
    constexpr int NC   = 80;
    constexpr int CH   = 85;
    constexpr int P    = 64 * 64;                  // 4096 positions per (b,a)
    constexpr int Btot = 16;
    constexpr int CONF_OFF = Btot * A * P * 4;     // 786432
    constexpr int CLS_OFF  = CONF_OFF + Btot * A * P; // 983040

    __shared__ float4 tile4[CH * PITCH4];          // 85 x 17 float4 = 22.6 KB
    float* tile = reinterpret_cast<float*>(tile4);

    const int blk = blockIdx.x;
    const int ba  = blk >> 6;                      // 64 tiles per (b,a)
    const int p0  = (blk & 63) * TP;
    const int t   = threadIdx.x;

    // ---- Load: 85 ch x 16 float4, all shift/mask addressing ----
    const float4* xin4 = reinterpret_cast<const float4*>(
        x + (size_t)ba * CH * P + p0);             // p0 multiple of 64 -> aligned
    #pragma unroll
    for (int k = 0; k < 6; k++) {
        const int idx = t + k * NT;                // 0..1535, need < 1360
        if (idx < CH * (TP / 4)) {
            const int c = idx >> 4;                // TP/4 = 16
            const int q = idx & 15;
            tile4[c * PITCH4 + q] = xin4[c * (P / 4) + q];
        }
    }
    __syncthreads();

    // ---- cls: 4 threads per position, 5 x STG.128 each, no divisions ----
    {
        const int p  = t >> 2;                     // 0..63
        const int j0 = t & 3;
        const float* trow = tile + p;              // tile[c][p] = tile[c*PITCH + p]
        float4* ocls4 = reinterpret_cast<float4*>(
            out + CLS_OFF + (size_t)(ba * P + p0 + p) * NC);
        #pragma unroll
        for (int k = 0; k < 5; k++) {
            const int j = j0 + 4 * k;              // float4 chunk 0..19
            const int c = 5 + 4 * j;               // channels c..c+3
            float4 v;
            v.x = sigf(trow[(c + 0) * PITCH]);
            v.y = sigf(trow[(c + 1) * PITCH]);
            v.z = sigf(trow[(c + 2) * PITCH]);
            v.w = sigf(trow[(c + 3) * PITCH]);
            ocls4[j] = v;
        }
    }

    // ---- boxes: threads 0..63, one STG.128 per position ----
    if (t < TP) {
        const int a  = ba - (ba / A) * A;
        const float aw = __ldg(anchors + a * 2 + 0);
        const float ah = __ldg(anchors + a * 2 + 1);
        const int pg = p0 + t;
        float4 b;
        b.x = (sigf(tile[0 * PITCH + t]) + (float)(pg >> 6)) * (1.0f / 64.0f);
        b.y = (sigf(tile[1 * PITCH + t]) + (float)(pg & 63)) * (1.0f / 64.0f);
        b.z = __expf(tile[2 * PITCH + t]) * aw;
        b.w = __expf(tile[3 * PITCH + t]) * ah;
        reinterpret_cast<float4*>(out)[ba * P + pg] = b;
    }
    // ---- conf: threads 64..79, LDS.128 + STG.128 ----
    else if (t < TP + TP / 4) {
        const int q = t - TP;                      // 0..15
        float4 v = tile4[4 * PITCH4 + q];          // channel 4, float4-aligned
        v.x = sigf(v.x);
        v.y = sigf(v.y);
        v.z = sigf(v.z);
        v.w = sigf(v.w);
        reinterpret_cast<float4*>(out + CONF_OFF + ba * P + p0)[q] = v;
    }
}

extern "C" void kernel_launch(void* const* d_in, const int* in_sizes, int n_in,
                              void* d_out, int out_size) {
    const float* x       = (const float*)d_in[0];
    const float* anchors = (const float*)d_in[1];
    float*       out     = (float*)d_out;
    yolo_kernel<<<3072, NT>>>(x, anchors, out);
}

// round 8
// speedup vs baseline: 1.4189x; 1.0115x over previous
#include <cuda_runtime.h>
#include <cuda_bf16.h>

// YOLO layer: x [B=16, C=255, 64, 64] fp32, anchors [3,2] fp32.
// pred = x.reshape(B, 3, 85, 64, 64).transpose(0,1,3,4,2)
// Outputs concatenated in d_out (float32):
//   boxes [B,3,64,64,4]  : 786,432    elems at offset 0
//   conf  [B,3,64,64]    : 196,608    elems at offset 786,432
//   cls   [B,3,64,64,80] : 15,728,640 elems at offset 983,040
//
// R7 changes vs R5 (20.8us kernel, DRAM 52%, L1 50%, issue 32%):
//  1. sigmoid via MUFU.TANH: sig(x) = fma(0.5, tanh(0.5x), 0.5).
//     1 MUFU/sigmoid instead of 2 (EX2+RCP) -> MUFU pipe busy ~6.7us -> ~3.4us.
//  2. cls thread remap for conflict-free scalar LDS: per warp, p spans 16
//     consecutive values (t>>1) and j0 = t&1 -> bank = const + 16*j0 + p
//     covers all 32 banks. Old mapping (4 j-lanes/position) was 2-way
//     conflicted (16j mod 32 in {0,16}).

#define NT 256
#define TP 64
#define PITCH 68            // floats per smem channel row (16 f4 data + 1 f4 pad)
#define PITCH4 17           // float4s per row

__device__ __forceinline__ float sigf(float v) {
    float t;
    asm("tanh.approx.f32 %0, %1;" : "=f"(t) : "f"(v * 0.5f));
    return fmaf(0.5f, t, 0.5f);          // FMUL + MUFU.TANH + FFMA
}

__global__ __launch_bounds__(NT) void yolo_kernel(
    const float* __restrict__ x,
    const float* __restrict__ anchors,
    float* __restrict__ out)
{
    constexpr int A    = 3;
    constexpr int NC   = 80;
    constexpr int CH   = 85;
    constexpr int P    = 64 * 64;                     // 4096 positions per (b,a)
    constexpr int Btot = 16;
    constexpr int CONF_OFF = Btot * A * P * 4;        // 786432
    constexpr int CLS_OFF  = CONF_OFF + Btot * A * P; // 983040

    __shared__ float4 tile4[CH * PITCH4];             // 85 x 17 float4 = 22.6 KB
    float* tile = reinterpret_cast<float*>(tile4);

    const int blk = blockIdx.x;
    const int ba  = blk >> 6;                         // 64 tiles per (b,a)
    const int p0  = (blk & 63) * TP;
    const int t   = threadIdx.x;

    // ---- Load: 85 ch x 16 float4, shift/mask addressing, LDG.128+STS.128 ----
    const float4* xin4 = reinterpret_cast<const float4*>(
        x + (size_t)ba * CH * P + p0);                // p0 multiple of 64 -> aligned
    #pragma unroll
    for (int k = 0; k < 6; k++) {
        const int idx = t + k * NT;                   // 0..1535, need < 1360
        if (idx < CH * (TP / 4)) {
            const int c = idx >> 4;                   // TP/4 = 16
            const int q = idx & 15;
            tile4[c * PITCH4 + q] = xin4[c * (P / 4) + q];
        }
    }
    __syncthreads();

    // ---- cls: conflict-free scalar LDS, 5 x STG.128 per thread ----
    // thread -> position p = (t>>1)&63, parity j0 = t&1, half h = t>>7.
    // chunks j = j0 + 2k + 10h (k=0..4). Warp: p spans 16 consecutive,
    // j0 in {0,1} -> LDS banks = const + 16*j0 + p: all 32 distinct.
    {
        const int p  = (t >> 1) & 63;
        const int j0 = t & 1;
        const int h  = t >> 7;                        // 0 or 1
        const float* trow = tile + p;                 // tile[c][p] = tile[c*PITCH + p]
        float4* ocls4 = reinterpret_cast<float4*>(
            out + CLS_OFF + (size_t)(ba * P + p0 + p) * NC);
        #pragma unroll
        for (int k = 0; k < 5; k++) {
            const int j = j0 + 2 * k + 10 * h;        // float4 chunk 0..19
            const int c = 5 + 4 * j;                  // channels c..c+3
            float4 v;
            v.x = sigf(trow[(c + 0) * PITCH]);
            v.y = sigf(trow[(c + 1) * PITCH]);
            v.z = sigf(trow[(c + 2) * PITCH]);
            v.w = sigf(trow[(c + 3) * PITCH]);
            ocls4[j] = v;
        }
    }

    // ---- boxes: threads 0..63, one STG.128 per position ----
    if (t < TP) {
        const int a  = ba - (ba / A) * A;
        const float aw = __ldg(anchors + a * 2 + 0);
        const float ah = __ldg(anchors + a * 2 + 1);
        const int pg = p0 + t;
        float4 b;
        b.x = (sigf(tile[0 * PITCH + t]) + (float)(pg >> 6)) * (1.0f / 64.0f);
        b.y = (sigf(tile[1 * PITCH + t]) + (float)(pg & 63)) * (1.0f / 64.0f);
        b.z = __expf(tile[2 * PITCH + t]) * aw;
        b.w = __expf(tile[3 * PITCH + t]) * ah;
        reinterpret_cast<float4*>(out)[ba * P + pg] = b;
    }
    // ---- conf: threads 64..79, LDS.128 + STG.128 ----
    else if (t < TP + TP / 4) {
        const int q = t - TP;                         // 0..15
        float4 v = tile4[4 * PITCH4 + q];             // channel 4, float4-aligned
        v.x = sigf(v.x);
        v.y = sigf(v.y);
        v.z = sigf(v.z);
        v.w = sigf(v.w);
        reinterpret_cast<float4*>(out + CONF_OFF + ba * P + p0)[q] = v;
    }
}

extern "C" void kernel_launch(void* const* d_in, const int* in_sizes, int n_in,
                              void* d_out, int out_size) {
    const float* x       = (const float*)d_in[0];
    const float* anchors = (const float*)d_in[1];
    float*       out     = (float*)d_out;
    yolo_kernel<<<3072, NT>>>(x, anchors, out);
}